// round 16
// baseline (speedup 1.0000x reference)
#include <cuda_runtime.h>

#define N_MAX 128
#define BB 4
#define BH 136
#define BW 200
#define OUT 56
#define CO 14
#define IMG_H 544
#define IMG_W 800
#define BF_STRIDE (1 + 4 + BB * CO * CO) /* 789 */
#define NCHUNK 2

// Per-ROI paste region: 384 x 256 px; tiles of 128 px x 32 rows.
#define XT 3
#define YT 8

// Mask storage as horizontal PAIRS: g_mpair[n][r][c] = (m[r][c], m[r][c+1]),
// padded layout (data rows 1..56, cols 1..56; borders zero). One aligned
// LDG.64 per bilinear x-tap pair.
#define MROWS 58
#define MPITCH 64
__device__ float2 g_mpair[N_MAX * MROWS * MPITCH];

// ---------------------------------------------------------------------------
// Kernel 1: fused roi_align + coeff upsample + softmax + sigmoid, staged in
// smem per 8-row chunk, emitted as float2 pairs. Grid (n_roi, 7), block 256.
// ---------------------------------------------------------------------------
__global__ void masks_kernel(const float* __restrict__ bases,
                             const float* __restrict__ bf) {
    int n = blockIdx.x;
    int chunk = blockIdx.y;                  // 0..6, 8 mask rows each
    const float* row = bf + (size_t)n * BF_STRIDE;
    float2* mpair = g_mpair + (size_t)n * MROWS * MPITCH;

    __shared__ float s_top[BB * CO * CO];
    __shared__ float s_m[8][MPITCH];         // padded cols 0..63, this chunk

    for (int i = threadIdx.x; i < BB * CO * CO; i += blockDim.x)
        s_top[i] = row[5 + i];
    for (int i = threadIdx.x; i < 8 * MPITCH; i += blockDim.x)
        ((float*)s_m)[i] = 0.0f;

    // Border rows of the padded layout (rows 0 and 57): zero pairs.
    if (chunk == 0 && threadIdx.x < 2 * MPITCH) {
        int r = (threadIdx.x >> 6) ? 57 : 0;
        int c = threadIdx.x & 63;
        mpair[r * MPITCH + c] = make_float2(0.0f, 0.0f);
    }
    __syncthreads();

    int bidx = (int)row[0];
    float bx0 = row[1], by0 = row[2], bx1 = row[3], by1 = row[4];
    const float* feat = bases + (size_t)bidx * (BB * BH * BW);

    float sx0 = bx0 * 0.25f - 0.5f;
    float sy0 = by0 * 0.25f - 0.5f;
    float sx1 = bx1 * 0.25f - 0.5f;
    float sy1 = by1 * 0.25f - 0.5f;
    float bwd = (sx1 - sx0) * (1.0f / OUT);
    float bhd = (sy1 - sy0) * (1.0f / OUT);

    int p0 = chunk * 448;
    for (int t = threadIdx.x; t < 448; t += blockDim.x) {
        int p = p0 + t;
        int i = p / OUT;
        int j = p - i * OUT;

        float ys = sy0 + (i + 0.5f) * bhd;
        float xs = sx0 + (j + 0.5f) * bwd;
        bool valid = (ys >= -1.0f) && (ys <= (float)BH) &&
                     (xs >= -1.0f) && (xs <= (float)BW);
        float yc = fminf(fmaxf(ys, 0.0f), (float)(BH - 1));
        float xc = fminf(fmaxf(xs, 0.0f), (float)(BW - 1));
        int yl = min((int)yc, BH - 2);
        int xl = min((int)xc, BW - 2);
        float ly = yc - (float)yl, hy = 1.0f - ly;
        float lx = xc - (float)xl, hx = 1.0f - lx;

        float cy = fminf(fmaxf((i + 0.5f) * 0.25f - 0.5f, 0.0f), (float)(CO - 1));
        float cx = fminf(fmaxf((j + 0.5f) * 0.25f - 0.5f, 0.0f), (float)(CO - 1));
        int cyl = min((int)cy, CO - 2);
        int cxl = min((int)cx, CO - 2);
        float ty = cy - (float)cyl, sy = 1.0f - ty;
        float tx = cx - (float)cxl, sx = 1.0f - tx;

        float roi[BB], cf[BB];
#pragma unroll
        for (int b = 0; b < BB; b++) {
            const float* f = feat + b * BH * BW + yl * BW + xl;
            float fll = __ldg(f);
            float flh = __ldg(f + 1);
            float fhl = __ldg(f + BW);
            float fhh = __ldg(f + BW + 1);
            float v = hy * (hx * fll + lx * flh) + ly * (hx * fhl + lx * fhh);
            roi[b] = valid ? v : 0.0f;

            const float* tp = s_top + b * CO * CO + cyl * CO + cxl;
            cf[b] = sy * (sx * tp[0] + tx * tp[1]) + ty * (sx * tp[CO] + tx * tp[CO + 1]);
        }

        float m = fmaxf(fmaxf(cf[0], cf[1]), fmaxf(cf[2], cf[3]));
        float e0 = __expf(cf[0] - m), e1 = __expf(cf[1] - m);
        float e2 = __expf(cf[2] - m), e3 = __expf(cf[3] - m);
        float inv = 1.0f / (e0 + e1 + e2 + e3);
        float dot = (roi[0] * e0 + roi[1] * e1 + roi[2] * e2 + roi[3] * e3) * inv;
        s_m[i - chunk * 8][j + 1] = 1.0f / (1.0f + __expf(-dot));
    }
    __syncthreads();

    // Emit pairs: padded rows 1+chunk*8 .. 8+chunk*8, cols 0..63.
    float2* dstp = mpair + (size_t)(1 + chunk * 8) * MPITCH;
    for (int idx = threadIdx.x; idx < 8 * MPITCH; idx += blockDim.x) {
        int r = idx >> 6;
        int c = idx & 63;
        float a = s_m[r][c];
        float b = (c < 63) ? s_m[r][c + 1] : 0.0f;
        dstp[r * MPITCH + c] = make_float2(a, b);
    }
}

// ---------------------------------------------------------------------------
// Kernel 2: paste for ROIs [roi_base, roi_base + gridDim.z). 4x4 patch per
// thread, slab early-exit, one LDG.64 per tap pair.
// Grid (XT, YT, chunk_rois), block (32, 8).
// ---------------------------------------------------------------------------
__global__ void __launch_bounds__(256, 8)
paste_box_kernel(const float* __restrict__ bf, float* __restrict__ out,
                 int roi_base) {
    int n = roi_base + blockIdx.z;
    const float* row = bf + (size_t)n * BF_STRIDE;
    float x0 = __ldg(row + 1), y0 = __ldg(row + 2);
    float x1 = __ldg(row + 3), y1 = __ldg(row + 4);

    int xs = max(0, ((int)floorf(x0) - 4)) & ~3;
    int ysr = max(0, (int)floorf(y0) - 4);

    float inv_h = __fdividef((float)OUT, y1 - y0);
    float inv_w = __fdividef((float)OUT, x1 - x0);

    // ---- Block-uniform slab liveness (128 px x 32 rows) ----
    int slabY = ysr + blockIdx.y * 32;
    float fyTop = ((float)slabY + 0.5f - y0) * inv_h - 0.5f;
    if (fyTop + 31.0f * inv_h <= -1.0f || fyTop >= (float)OUT) return;

    int slabX = xs + blockIdx.x * 128;
    float fxL = ((float)slabX + 0.5f - x0) * inv_w - 0.5f;
    if (fxL + 127.0f * inv_w <= -1.0f || fxL >= (float)OUT) return;

    // ---- Per-thread x setup (4 px) ----
    int x = slabX + threadIdx.x * 4;
    if (x + 3 >= IMG_W) return;

    float fxs = fxL + (float)(threadIdx.x * 4) * inv_w;
    if (fxs + 3.0f * inv_w <= -1.0f || fxs >= (float)OUT) return;  // memset covers

    int c[4];
    float w0[4], w1[4];
#pragma unroll
    for (int k = 0; k < 4; k++) {
        float fx = fxs + (float)k * inv_w;
        bool valid = (fx > -1.0f) && (fx < (float)OUT);
        float fmx = floorf(fx);
        float wx1 = fx - fmx, wx0 = 1.0f - wx1;
        c[k] = min(max((int)fmx, -1), 61) + 1;   // 0..62
        w0[k] = valid ? wx0 : 0.0f;
        w1[k] = valid ? wx1 : 0.0f;
    }

    // ---- 4 rows ----
    int ybase = slabY + threadIdx.y * 4;
    float fy = fyTop + (float)(threadIdx.y * 4) * inv_h;
    const float2* Mb = g_mpair + (size_t)n * MROWS * MPITCH;
    float* orow = out + (size_t)n * (IMG_H * IMG_W) + (size_t)ybase * IMG_W + x;

#pragma unroll
    for (int r = 0; r < 4; r++, orow += IMG_W, fy += inv_h) {
        int y = ybase + r;
        if (y >= IMG_H) break;
        if (fy <= -1.0f || fy >= (float)OUT) continue;   // memset covers

        float fmy = floorf(fy);
        float wy1 = fy - fmy, wy0 = 1.0f - wy1;
        const float2* M0 = Mb + ((int)fmy + 1) * MPITCH;
        const float2* M1 = M0 + MPITCH;

        float v[4];
#pragma unroll
        for (int k = 0; k < 4; k++) {
            float2 q0 = __ldg(M0 + c[k]);
            float2 q1 = __ldg(M1 + c[k]);
            v[k] = wy0 * (w0[k] * q0.x + w1[k] * q0.y) +
                   wy1 * (w0[k] * q1.x + w1[k] * q1.y);
        }
        *(float4*)orow = make_float4(v[0], v[1], v[2], v[3]);
    }
}

// ---------------------------------------------------------------------------
// Static streams + events (module init; not device allocations). Both work
// branches on non-default streams — R14 proved memset/kernel overlap works
// in this topology; the fix here is only 2 paste chunks (paste launches have
// a ~10us latency floor regardless of grid size).
// ---------------------------------------------------------------------------
struct HxRes {
    cudaStream_t sM, sC;
    cudaEvent_t fork, join, evM[NCHUNK];
    HxRes() {
        cudaStreamCreateWithFlags(&sM, cudaStreamNonBlocking);
        cudaStreamCreateWithFlags(&sC, cudaStreamNonBlocking);
        cudaEventCreateWithFlags(&fork, cudaEventDisableTiming);
        cudaEventCreateWithFlags(&join, cudaEventDisableTiming);
        for (int k = 0; k < NCHUNK; k++)
            cudaEventCreateWithFlags(&evM[k], cudaEventDisableTiming);
    }
};
static HxRes hx;

extern "C" void kernel_launch(void* const* d_in, const int* in_sizes, int n_in,
                              void* d_out, int out_size) {
    const float* bases = (const float*)d_in[0];
    const float* bf = (const float*)d_in[1];
    int n_roi = in_sizes[1] / BF_STRIDE;
    if (n_roi > N_MAX) n_roi = N_MAX;

    const size_t roi_bytes = (size_t)IMG_H * IMG_W * sizeof(float);
    int per = (n_roi + NCHUNK - 1) / NCHUNK;

    cudaEventRecord(hx.fork, 0);
    cudaStreamWaitEvent(hx.sM, hx.fork, 0);
    cudaStreamWaitEvent(hx.sC, hx.fork, 0);

    // Stream M: two memset halves (per-ROI slices).
    for (int k = 0; k < NCHUNK; k++) {
        int r0 = k * per;
        int cnt = min(per, n_roi - r0);
        if (cnt <= 0) { cudaEventRecord(hx.evM[k], hx.sM); continue; }
        cudaMemsetAsync((char*)d_out + (size_t)r0 * roi_bytes, 0,
                        (size_t)cnt * roi_bytes, hx.sM);
        cudaEventRecord(hx.evM[k], hx.sM);
    }

    // Stream C: masks for all ROIs (hidden under memset half 0), then paste
    // half k once its slice is zeroed.
    dim3 mgrid(n_roi, 7);
    masks_kernel<<<mgrid, 256, 0, hx.sC>>>(bases, bf);

    dim3 pblock(32, 8);
    for (int k = 0; k < NCHUNK; k++) {
        int r0 = k * per;
        int cnt = min(per, n_roi - r0);
        if (cnt <= 0) continue;
        cudaStreamWaitEvent(hx.sC, hx.evM[k], 0);
        dim3 pgrid(XT, YT, cnt);
        paste_box_kernel<<<pgrid, pblock, 0, hx.sC>>>(bf, (float*)d_out, r0);
    }

    cudaEventRecord(hx.join, hx.sC);
    cudaStreamWaitEvent(0, hx.join, 0);
}

// round 17
// speedup vs baseline: 1.0967x; 1.0967x over previous
#include <cuda_runtime.h>

#define N_MAX 128
#define BB 4
#define BH 136
#define BW 200
#define OUT 56
#define CO 14
#define IMG_H 544
#define IMG_W 800
#define BF_STRIDE (1 + 4 + BB * CO * CO) /* 789 */

// Per-ROI paste region: 384 x 256 px; tiles of 128 px x 32 rows.
#define XT 3
#define YT 8

// Mask storage as horizontal PAIRS: g_mpair[n][r][c] = (m[r][c], m[r][c+1]),
// padded layout (data rows 1..56, cols 1..56; borders zero).
#define MROWS 58
#define MPITCH 64
__device__ float2 g_mpair[N_MAX * MROWS * MPITCH];

// Per-ROI paste params, precomputed in masks_kernel:
//   g_prm[n] = (x0, y0, inv_w, inv_h);  g_anc[n] = (xs, ysr, -, -)
__device__ float4 g_prm[N_MAX];
__device__ float4 g_anc[N_MAX];

// ---------------------------------------------------------------------------
// Kernel 1: fused roi_align + coeff upsample + softmax + sigmoid, staged in
// smem per 8-row chunk, emitted as float2 pairs. Chunk 0 also writes the
// per-ROI paste params. Grid (n_roi, 7), block 256.
// ---------------------------------------------------------------------------
__global__ void masks_kernel(const float* __restrict__ bases,
                             const float* __restrict__ bf) {
    int n = blockIdx.x;
    int chunk = blockIdx.y;                  // 0..6, 8 mask rows each
    const float* row = bf + (size_t)n * BF_STRIDE;
    float2* mpair = g_mpair + (size_t)n * MROWS * MPITCH;

    __shared__ float s_top[BB * CO * CO];
    __shared__ float s_m[8][MPITCH];

    for (int i = threadIdx.x; i < BB * CO * CO; i += blockDim.x)
        s_top[i] = row[5 + i];
    for (int i = threadIdx.x; i < 8 * MPITCH; i += blockDim.x)
        ((float*)s_m)[i] = 0.0f;

    if (chunk == 0 && threadIdx.x < 2 * MPITCH) {
        int r = (threadIdx.x >> 6) ? 57 : 0;
        int c = threadIdx.x & 63;
        mpair[r * MPITCH + c] = make_float2(0.0f, 0.0f);
    }
    __syncthreads();

    int bidx = (int)row[0];
    float bx0 = row[1], by0 = row[2], bx1 = row[3], by1 = row[4];
    const float* feat = bases + (size_t)bidx * (BB * BH * BW);

    // Per-ROI paste params (one thread).
    if (chunk == 0 && threadIdx.x == 0) {
        float inv_w = __fdividef((float)OUT, bx1 - bx0);
        float inv_h = __fdividef((float)OUT, by1 - by0);
        int axs = max(0, ((int)floorf(bx0) - 4)) & ~3;
        int ays = max(0, (int)floorf(by0) - 4);
        g_prm[n] = make_float4(bx0, by0, inv_w, inv_h);
        g_anc[n] = make_float4((float)axs, (float)ays, 0.0f, 0.0f);
    }

    float sx0 = bx0 * 0.25f - 0.5f;
    float sy0 = by0 * 0.25f - 0.5f;
    float sx1 = bx1 * 0.25f - 0.5f;
    float sy1 = by1 * 0.25f - 0.5f;
    float bwd = (sx1 - sx0) * (1.0f / OUT);
    float bhd = (sy1 - sy0) * (1.0f / OUT);

    int p0 = chunk * 448;
    for (int t = threadIdx.x; t < 448; t += blockDim.x) {
        int p = p0 + t;
        int i = p / OUT;
        int j = p - i * OUT;

        float ys = sy0 + (i + 0.5f) * bhd;
        float xs = sx0 + (j + 0.5f) * bwd;
        bool valid = (ys >= -1.0f) && (ys <= (float)BH) &&
                     (xs >= -1.0f) && (xs <= (float)BW);
        float yc = fminf(fmaxf(ys, 0.0f), (float)(BH - 1));
        float xc = fminf(fmaxf(xs, 0.0f), (float)(BW - 1));
        int yl = min((int)yc, BH - 2);
        int xl = min((int)xc, BW - 2);
        float ly = yc - (float)yl, hy = 1.0f - ly;
        float lx = xc - (float)xl, hx = 1.0f - lx;

        float cy = fminf(fmaxf((i + 0.5f) * 0.25f - 0.5f, 0.0f), (float)(CO - 1));
        float cx = fminf(fmaxf((j + 0.5f) * 0.25f - 0.5f, 0.0f), (float)(CO - 1));
        int cyl = min((int)cy, CO - 2);
        int cxl = min((int)cx, CO - 2);
        float ty = cy - (float)cyl, sy = 1.0f - ty;
        float tx = cx - (float)cxl, sx = 1.0f - tx;

        float roi[BB], cf[BB];
#pragma unroll
        for (int b = 0; b < BB; b++) {
            const float* f = feat + b * BH * BW + yl * BW + xl;
            float fll = __ldg(f);
            float flh = __ldg(f + 1);
            float fhl = __ldg(f + BW);
            float fhh = __ldg(f + BW + 1);
            float v = hy * (hx * fll + lx * flh) + ly * (hx * fhl + lx * fhh);
            roi[b] = valid ? v : 0.0f;

            const float* tp = s_top + b * CO * CO + cyl * CO + cxl;
            cf[b] = sy * (sx * tp[0] + tx * tp[1]) + ty * (sx * tp[CO] + tx * tp[CO + 1]);
        }

        float m = fmaxf(fmaxf(cf[0], cf[1]), fmaxf(cf[2], cf[3]));
        float e0 = __expf(cf[0] - m), e1 = __expf(cf[1] - m);
        float e2 = __expf(cf[2] - m), e3 = __expf(cf[3] - m);
        float inv = 1.0f / (e0 + e1 + e2 + e3);
        float dot = (roi[0] * e0 + roi[1] * e1 + roi[2] * e2 + roi[3] * e3) * inv;
        s_m[i - chunk * 8][j + 1] = 1.0f / (1.0f + __expf(-dot));
    }
    __syncthreads();

    float2* dstp = mpair + (size_t)(1 + chunk * 8) * MPITCH;
    for (int idx = threadIdx.x; idx < 8 * MPITCH; idx += blockDim.x) {
        int r = idx >> 6;
        int c = idx & 63;
        float a = s_m[r][c];
        float b = (c < 63) ? s_m[r][c + 1] : 0.0f;
        dstp[r * MPITCH + c] = make_float2(a, b);
    }
}

// ---------------------------------------------------------------------------
// Kernel 2: paste. 4x4 patch per thread, slab early-exit, BRANCHLESS row
// body: row weights zeroed when fy invalid, row index clamped into the
// padded mask, stores predicated only on y < IMG_H. All 4 rows' loads can
// issue together. Grid (XT, YT, n_roi), block (32, 8).
// ---------------------------------------------------------------------------
__global__ void __launch_bounds__(256, 6)
paste_box_kernel(float* __restrict__ out) {
    int n = blockIdx.z;
    float4 prm = __ldg(&g_prm[n]);           // x0, y0, inv_w, inv_h
    float4 anc = __ldg(&g_anc[n]);           // xs, ysr
    float x0 = prm.x, y0 = prm.y, inv_w = prm.z, inv_h = prm.w;
    int xs = (int)anc.x, ysr = (int)anc.y;

    // ---- Block-uniform slab liveness (128 px x 32 rows) ----
    int slabY = ysr + blockIdx.y * 32;
    float fyTop = ((float)slabY + 0.5f - y0) * inv_h - 0.5f;
    if (fyTop + 31.0f * inv_h <= -1.0f || fyTop >= (float)OUT) return;

    int slabX = xs + blockIdx.x * 128;
    float fxL = ((float)slabX + 0.5f - x0) * inv_w - 0.5f;
    if (fxL + 127.0f * inv_w <= -1.0f || fxL >= (float)OUT) return;

    // ---- Per-thread x setup (4 px) ----
    int x = slabX + threadIdx.x * 4;
    if (x + 3 >= IMG_W) return;

    float fxs = fxL + (float)(threadIdx.x * 4) * inv_w;
    if (fxs + 3.0f * inv_w <= -1.0f || fxs >= (float)OUT) return;  // memset covers

    int c[4];
    float w0[4], w1[4];
#pragma unroll
    for (int k = 0; k < 4; k++) {
        float fx = fxs + (float)k * inv_w;
        bool valid = (fx > -1.0f) && (fx < (float)OUT);
        float fmx = floorf(fx);
        float wx1 = fx - fmx, wx0 = 1.0f - wx1;
        c[k] = min(max((int)fmx, -1), 61) + 1;   // 0..62
        w0[k] = valid ? wx0 : 0.0f;
        w1[k] = valid ? wx1 : 0.0f;
    }

    // ---- 4 rows, branchless ----
    int ybase = slabY + threadIdx.y * 4;
    float fy0 = fyTop + (float)(threadIdx.y * 4) * inv_h;
    const float2* Mb = g_mpair + (size_t)n * MROWS * MPITCH;
    float* orow = out + (size_t)n * (IMG_H * IMG_W) + (size_t)ybase * IMG_W + x;

    int roff[4];
    float wy0[4], wy1[4];
#pragma unroll
    for (int r = 0; r < 4; r++) {
        float fy = fy0 + (float)r * inv_h;
        bool rv = (fy > -1.0f) && (fy < (float)OUT);
        float fmy = floorf(fy);
        float a = fy - fmy;
        roff[r] = (min(max((int)fmy, -1), 55) + 1) * MPITCH;  // rows 0..56
        wy1[r] = rv ? a : 0.0f;
        wy0[r] = rv ? (1.0f - a) : 0.0f;
    }

#pragma unroll
    for (int r = 0; r < 4; r++) {
        const float2* M0 = Mb + roff[r];
        const float2* M1 = M0 + MPITCH;
        float v[4];
#pragma unroll
        for (int k = 0; k < 4; k++) {
            float2 q0 = __ldg(M0 + c[k]);
            float2 q1 = __ldg(M1 + c[k]);
            v[k] = wy0[r] * (w0[k] * q0.x + w1[k] * q0.y) +
                   wy1[r] * (w0[k] * q1.x + w1[k] * q1.y);
        }
        if (ybase + r < IMG_H)
            *(float4*)(orow + r * IMG_W) = make_float4(v[0], v[1], v[2], v[3]);
    }
}

extern "C" void kernel_launch(void* const* d_in, const int* in_sizes, int n_in,
                              void* d_out, int out_size) {
    const float* bases = (const float*)d_in[0];
    const float* bf = (const float*)d_in[1];
    int n_roi = in_sizes[1] / BF_STRIDE;
    if (n_roi > N_MAX) n_roi = N_MAX;

    // Serial pipeline — overlap rejected after 5 failed experiments.
    cudaMemsetAsync(d_out, 0, (size_t)out_size * sizeof(float));

    dim3 mgrid(n_roi, 7);
    masks_kernel<<<mgrid, 256>>>(bases, bf);

    dim3 pblock(32, 8);
    dim3 pgrid(XT, YT, n_roi);
    paste_box_kernel<<<pgrid, pblock>>>((float*)d_out);
}